// round 15
// baseline (speedup 1.0000x reference)
#include <cuda_runtime.h>
#include <cuda_fp16.h>
#include <float.h>

#define C_DIM 512
#define H_DIM 50
#define W_DIM 75
#define HW_DIM (H_DIM * W_DIM)
#define NROI 512
#define PRE 14
#define PADH 264   // stage row stride in halves (= 528B, 16B-aligned)
#define CHUNK0 13  // first pixel-chunk size; remaining chunks are 12

// channels-last fp16 copy of the feature map: [H*W, C]
__device__ __align__(16) __half g_featT[HW_DIM * C_DIM];

// -------------------------------------------------------------------------
// Tiled transpose + fp16 quantize: bottom [C, H*W] -> g_featT [H*W, C]
// -------------------------------------------------------------------------
__global__ void transpose_kernel(const float* __restrict__ in) {
    __shared__ float tile[64][33];
    int hw0 = blockIdx.x * 32;
    int c0  = blockIdx.y * 64;
    int tx = threadIdx.x, ty = threadIdx.y;

    #pragma unroll
    for (int j = 0; j < 64; j += 8) {
        int hw = hw0 + tx;
        int c  = c0 + ty + j;
        if (hw < HW_DIM) tile[ty + j][tx] = in[c * HW_DIM + hw];
    }
    __syncthreads();
    #pragma unroll
    for (int j = 0; j < 32; j += 8) {
        int hw = hw0 + ty + j;
        if (hw < HW_DIM) {
            __half2 v = __floats2half2_rn(tile[2 * tx][ty + j],
                                          tile[2 * tx + 1][ty + j]);
            *reinterpret_cast<__half2*>(&g_featT[hw * C_DIM + c0 + 2 * tx]) = v;
        }
    }
}

// -------------------------------------------------------------------------
// Main kernel: grid (512 rois, 2 channel-halves), 128 threads (4 warps).
// Lane owns 8 consecutive channels (16B fp16 LDG.128); warp covers a
// 256-channel half; warps split pixels round-robin. The 49 pixels are
// processed in FOUR chunks (13+12+12+12) so the stage is only ~6.9KB,
// leaving ~177KB of L1D carveout for the gather working set.
// R9 hot loop verbatim: offsets+weights in registers, 4x4-load batches.
// -------------------------------------------------------------------------
__global__ __launch_bounds__(128, 7) void roi_pool_kernel(
    const float* __restrict__ rois, float* __restrict__ out) {

    // Packed corner tables: (.x = off0 bits, .y = off1 bits, .z = w0, .w = w1),
    // offsets in 8-channel (uint4) units.
    __shared__ float4 tabx[PRE], taby[PRE];
    __shared__ __align__(16) __half stage[CHUNK0 * PADH];

    const int n = blockIdx.x;
    const int t = threadIdx.x;

    // ---- per-ROI corner tables (threads 0..27) ----
    if (t < 2 * PRE) {
        const int axis = (t >= PRE);          // 0 = x, 1 = y
        const int i = axis ? (t - PRE) : t;
        const float lo = rois[n * 5 + (axis ? 2 : 1)] * (1.0f / 16.0f);
        const float hi = rois[n * 5 + (axis ? 4 : 3)] * (1.0f / 16.0f);
        const int D = axis ? H_DIM : W_DIM;

        // replicate reference math exactly
        float s  = (hi - lo) / (float)(D - 1);
        float tt = (lo + hi - (float)(D - 1)) / (float)(D - 1);
        float base = -1.0f + (float)i * (2.0f / 13.0f);
        float g  = s * base + tt;
        float xc = (g + 1.0f) * 0.5f * (float)(D - 1);

        float f0 = floorf(xc);
        int   i0 = (int)f0;
        float w1 = xc - f0;
        float w0 = 1.0f - w1;
        float v0 = (i0 >= 0 && i0 <= D - 1) ? 1.0f : 0.0f;
        float v1 = (i0 + 1 >= 0 && i0 + 1 <= D - 1) ? 1.0f : 0.0f;
        int c0 = min(max(i0, 0), D - 1);
        int c1 = min(max(i0 + 1, 0), D - 1);

        int mul = axis ? (W_DIM * (C_DIM / 8)) : (C_DIM / 8);
        float4 e;
        e.x = __int_as_float(c0 * mul);
        e.y = __int_as_float(c1 * mul);
        e.z = w0 * v0;
        e.w = w1 * v1;
        if (axis) taby[i] = e; else tabx[i] = e;
    }
    __syncthreads();

    const int w    = t >> 5;
    const int lane = t & 31;
    const uint4* __restrict__ fb =
        (const uint4*)g_featT + blockIdx.y * 32 + lane;

    const __half2 HMIN = __float2half2_rn(-60000.0f);

    float* __restrict__ ob = out + (size_t)n * (C_DIM * 49)
                                 + (size_t)blockIdx.y * (256 * 49);

    #pragma unroll
    for (int chunk = 0; chunk < 4; chunk++) {
        const int pb = chunk ? (CHUNK0 + 12 * (chunk - 1)) : 0;
        const int np = chunk ? 12 : CHUNK0;

        // ---- compute this chunk's pixels ----
        for (int p = pb + w; p < pb + np; p += 4) {
            const int py = p / 7;
            const int px = p - py * 7;

            const float4 tx0 = tabx[2 * px];
            const float4 tx1 = tabx[2 * px + 1];
            const float4 ty0 = taby[2 * py];
            const float4 ty1 = taby[2 * py + 1];

            __half2 m0 = HMIN, m1 = HMIN, m2 = HMIN, m3 = HMIN;

            #pragma unroll
            for (int dy = 0; dy < 2; dy++) {
                const float4 ty = dy ? ty1 : ty0;
                const int oy0 = __float_as_int(ty.x);
                const int oy1 = __float_as_int(ty.y);
                const float wy0 = ty.z, wy1 = ty.w;
                #pragma unroll
                for (int dx = 0; dx < 2; dx++) {
                    const float4 tx = dx ? tx1 : tx0;
                    const int ox0 = __float_as_int(tx.x);
                    const int ox1 = __float_as_int(tx.y);

                    // 4 independent 16B gathers (8 fp16 channels each)
                    uint4 r00 = fb[oy0 + ox0];
                    uint4 r01 = fb[oy0 + ox1];
                    uint4 r10 = fb[oy1 + ox0];
                    uint4 r11 = fb[oy1 + ox1];

                    // corner weights: fp32 products, broadcast to half2
                    const float wx0 = tx.z, wx1 = tx.w;
                    const __half2 w00 = __float2half2_rn(wy0 * wx0);
                    const __half2 w01 = __float2half2_rn(wy0 * wx1);
                    const __half2 w10 = __float2half2_rn(wy1 * wx0);
                    const __half2 w11 = __float2half2_rn(wy1 * wx1);

                    const __half2* h00 = reinterpret_cast<const __half2*>(&r00);
                    const __half2* h01 = reinterpret_cast<const __half2*>(&r01);
                    const __half2* h10 = reinterpret_cast<const __half2*>(&r10);
                    const __half2* h11 = reinterpret_cast<const __half2*>(&r11);

                    __half2 v0 = __hmul2(h00[0], w00);
                    __half2 v1 = __hmul2(h00[1], w00);
                    __half2 v2 = __hmul2(h00[2], w00);
                    __half2 v3 = __hmul2(h00[3], w00);
                    v0 = __hfma2(h01[0], w01, v0);
                    v1 = __hfma2(h01[1], w01, v1);
                    v2 = __hfma2(h01[2], w01, v2);
                    v3 = __hfma2(h01[3], w01, v3);
                    v0 = __hfma2(h10[0], w10, v0);
                    v1 = __hfma2(h10[1], w10, v1);
                    v2 = __hfma2(h10[2], w10, v2);
                    v3 = __hfma2(h10[3], w10, v3);
                    v0 = __hfma2(h11[0], w11, v0);
                    v1 = __hfma2(h11[1], w11, v1);
                    v2 = __hfma2(h11[2], w11, v2);
                    v3 = __hfma2(h11[3], w11, v3);

                    m0 = __hmax2(m0, v0);
                    m1 = __hmax2(m1, v1);
                    m2 = __hmax2(m2, v2);
                    m3 = __hmax2(m3, v3);
                }
            }

            // pixel-major fp16 stage: 16B STS, lane-consecutive -> conflict-free
            uint4 pk;
            pk.x = *reinterpret_cast<unsigned int*>(&m0);
            pk.y = *reinterpret_cast<unsigned int*>(&m1);
            pk.z = *reinterpret_cast<unsigned int*>(&m2);
            pk.w = *reinterpret_cast<unsigned int*>(&m3);
            *reinterpret_cast<uint4*>(&stage[(p - pb) * PADH + lane * 8]) = pk;
        }
        __syncthreads();

        // ---- coalesced writeback of this chunk: 128 channel-pairs x np
        // pixels; pair index = t + k*128 walked incrementally (p fastest).
        const int q = 128 / np;
        const int r = 128 - q * np;
        int c2 = t / np;
        int pp = t - c2 * np;
        for (int k = 0; k < np; k++) {
            unsigned int v = *reinterpret_cast<const unsigned int*>(
                &stage[pp * PADH + 2 * c2]);
            __half2 h = *reinterpret_cast<__half2*>(&v);
            float2 f = __half22float2(h);
            ob[(2 * c2) * 49 + pb + pp]     = f.x;
            ob[(2 * c2 + 1) * 49 + pb + pp] = f.y;
            pp += r; c2 += q;
            if (pp >= np) { pp -= np; c2 += 1; }
        }
        __syncthreads();
    }
}

// -------------------------------------------------------------------------
extern "C" void kernel_launch(void* const* d_in, const int* in_sizes, int n_in,
                              void* d_out, int out_size) {
    const float* bottom = (const float*)d_in[0];
    const float* rois   = (const float*)d_in[1];
    if (n_in >= 2 && in_sizes[0] == NROI * 5) {
        bottom = (const float*)d_in[1];
        rois   = (const float*)d_in[0];
    }
    float* out = (float*)d_out;

    dim3 tgrid((HW_DIM + 31) / 32, C_DIM / 64);
    transpose_kernel<<<tgrid, dim3(32, 8)>>>(bottom);

    dim3 rgrid(NROI, 2);
    roi_pool_kernel<<<rgrid, 128>>>(rois, out);
}

// round 16
// speedup vs baseline: 1.1298x; 1.1298x over previous
#include <cuda_runtime.h>
#include <cuda_fp16.h>
#include <float.h>

#define C_DIM 512
#define H_DIM 50
#define W_DIM 75
#define HW_DIM (H_DIM * W_DIM)
#define NROI 512
#define PRE 14
#define PADH 264   // stage row stride in halves (= 528B, 16B-aligned)

// channels-last fp16 copy of the feature map: [H*W, C]
__device__ __align__(16) __half g_featT[HW_DIM * C_DIM];

// -------------------------------------------------------------------------
// Tiled transpose + fp16 quantize: bottom [C, H*W] -> g_featT [H*W, C]
// -------------------------------------------------------------------------
__global__ void transpose_kernel(const float* __restrict__ in) {
    __shared__ float tile[64][33];
    int hw0 = blockIdx.x * 32;
    int c0  = blockIdx.y * 64;
    int tx = threadIdx.x, ty = threadIdx.y;

    #pragma unroll
    for (int j = 0; j < 64; j += 8) {
        int hw = hw0 + tx;
        int c  = c0 + ty + j;
        if (hw < HW_DIM) tile[ty + j][tx] = in[c * HW_DIM + hw];
    }
    __syncthreads();
    #pragma unroll
    for (int j = 0; j < 32; j += 8) {
        int hw = hw0 + ty + j;
        if (hw < HW_DIM) {
            __half2 v = __floats2half2_rn(tile[2 * tx][ty + j],
                                          tile[2 * tx + 1][ty + j]);
            *reinterpret_cast<__half2*>(&g_featT[hw * C_DIM + c0 + 2 * tx]) = v;
        }
    }
}

// 16B gather with L1 evict-last policy (keep feature map resident in L1).
// Non-volatile asm: ptxas may still reorder/batch the loads.
__device__ __forceinline__ uint4 ldg_keep(const uint4* p) {
    uint4 v;
    asm("ld.global.nc.L1::evict_last.v4.u32 {%0,%1,%2,%3}, [%4];"
        : "=r"(v.x), "=r"(v.y), "=r"(v.z), "=r"(v.w)
        : "l"(p));
    return v;
}

// -------------------------------------------------------------------------
// Main kernel: grid (512 rois, 2 channel-halves), 128 threads (4 warps).
// Lane owns 8 consecutive channels (16B fp16 LDG.128); warp covers a
// 256-channel half; warps split pixels round-robin. The 49 pixels are
// processed in TWO chunks (25 + 24): stage = 13.2KB -> ~130KB L1D carveout.
// R9 hot loop structure: offsets+weights in registers, 4x4-load batches,
// gathers tagged L1::evict_last.
// -------------------------------------------------------------------------
__global__ __launch_bounds__(128, 7) void roi_pool_kernel(
    const float* __restrict__ rois, float* __restrict__ out) {

    // Packed corner tables: (.x = off0 bits, .y = off1 bits, .z = w0, .w = w1),
    // offsets in 8-channel (uint4) units.
    __shared__ float4 tabx[PRE], taby[PRE];
    __shared__ __align__(16) __half stage[25 * PADH];

    const int n = blockIdx.x;
    const int t = threadIdx.x;

    // ---- per-ROI corner tables (threads 0..27) ----
    if (t < 2 * PRE) {
        const int axis = (t >= PRE);          // 0 = x, 1 = y
        const int i = axis ? (t - PRE) : t;
        const float lo = rois[n * 5 + (axis ? 2 : 1)] * (1.0f / 16.0f);
        const float hi = rois[n * 5 + (axis ? 4 : 3)] * (1.0f / 16.0f);
        const int D = axis ? H_DIM : W_DIM;

        // replicate reference math exactly
        float s  = (hi - lo) / (float)(D - 1);
        float tt = (lo + hi - (float)(D - 1)) / (float)(D - 1);
        float base = -1.0f + (float)i * (2.0f / 13.0f);
        float g  = s * base + tt;
        float xc = (g + 1.0f) * 0.5f * (float)(D - 1);

        float f0 = floorf(xc);
        int   i0 = (int)f0;
        float w1 = xc - f0;
        float w0 = 1.0f - w1;
        float v0 = (i0 >= 0 && i0 <= D - 1) ? 1.0f : 0.0f;
        float v1 = (i0 + 1 >= 0 && i0 + 1 <= D - 1) ? 1.0f : 0.0f;
        int c0 = min(max(i0, 0), D - 1);
        int c1 = min(max(i0 + 1, 0), D - 1);

        int mul = axis ? (W_DIM * (C_DIM / 8)) : (C_DIM / 8);
        float4 e;
        e.x = __int_as_float(c0 * mul);
        e.y = __int_as_float(c1 * mul);
        e.z = w0 * v0;
        e.w = w1 * v1;
        if (axis) taby[i] = e; else tabx[i] = e;
    }
    __syncthreads();

    const int w    = t >> 5;
    const int lane = t & 31;
    const uint4* __restrict__ fb =
        (const uint4*)g_featT + blockIdx.y * 32 + lane;

    const __half2 HMIN = __float2half2_rn(-60000.0f);

    float* __restrict__ ob = out + (size_t)n * (C_DIM * 49)
                                 + (size_t)blockIdx.y * (256 * 49);

    #pragma unroll
    for (int chunk = 0; chunk < 2; chunk++) {
        const int pb = chunk * 25;
        const int np = chunk ? 24 : 25;

        // ---- compute this chunk's pixels ----
        for (int p = pb + w; p < pb + np; p += 4) {
            const int py = p / 7;
            const int px = p - py * 7;

            const float4 tx0 = tabx[2 * px];
            const float4 tx1 = tabx[2 * px + 1];
            const float4 ty0 = taby[2 * py];
            const float4 ty1 = taby[2 * py + 1];

            __half2 m0 = HMIN, m1 = HMIN, m2 = HMIN, m3 = HMIN;

            #pragma unroll
            for (int dy = 0; dy < 2; dy++) {
                const float4 ty = dy ? ty1 : ty0;
                const int oy0 = __float_as_int(ty.x);
                const int oy1 = __float_as_int(ty.y);
                const float wy0 = ty.z, wy1 = ty.w;
                #pragma unroll
                for (int dx = 0; dx < 2; dx++) {
                    const float4 tx = dx ? tx1 : tx0;
                    const int ox0 = __float_as_int(tx.x);
                    const int ox1 = __float_as_int(tx.y);

                    // 4 independent 16B gathers (8 fp16 channels each),
                    // L1 evict-last to keep the feature map resident
                    uint4 r00 = ldg_keep(fb + (oy0 + ox0));
                    uint4 r01 = ldg_keep(fb + (oy0 + ox1));
                    uint4 r10 = ldg_keep(fb + (oy1 + ox0));
                    uint4 r11 = ldg_keep(fb + (oy1 + ox1));

                    // corner weights: fp32 products, broadcast to half2
                    const float wx0 = tx.z, wx1 = tx.w;
                    const __half2 w00 = __float2half2_rn(wy0 * wx0);
                    const __half2 w01 = __float2half2_rn(wy0 * wx1);
                    const __half2 w10 = __float2half2_rn(wy1 * wx0);
                    const __half2 w11 = __float2half2_rn(wy1 * wx1);

                    const __half2* h00 = reinterpret_cast<const __half2*>(&r00);
                    const __half2* h01 = reinterpret_cast<const __half2*>(&r01);
                    const __half2* h10 = reinterpret_cast<const __half2*>(&r10);
                    const __half2* h11 = reinterpret_cast<const __half2*>(&r11);

                    __half2 v0 = __hmul2(h00[0], w00);
                    __half2 v1 = __hmul2(h00[1], w00);
                    __half2 v2 = __hmul2(h00[2], w00);
                    __half2 v3 = __hmul2(h00[3], w00);
                    v0 = __hfma2(h01[0], w01, v0);
                    v1 = __hfma2(h01[1], w01, v1);
                    v2 = __hfma2(h01[2], w01, v2);
                    v3 = __hfma2(h01[3], w01, v3);
                    v0 = __hfma2(h10[0], w10, v0);
                    v1 = __hfma2(h10[1], w10, v1);
                    v2 = __hfma2(h10[2], w10, v2);
                    v3 = __hfma2(h10[3], w10, v3);
                    v0 = __hfma2(h11[0], w11, v0);
                    v1 = __hfma2(h11[1], w11, v1);
                    v2 = __hfma2(h11[2], w11, v2);
                    v3 = __hfma2(h11[3], w11, v3);

                    m0 = __hmax2(m0, v0);
                    m1 = __hmax2(m1, v1);
                    m2 = __hmax2(m2, v2);
                    m3 = __hmax2(m3, v3);
                }
            }

            // pixel-major fp16 stage: 16B STS, lane-consecutive -> conflict-free
            uint4 pk;
            pk.x = *reinterpret_cast<unsigned int*>(&m0);
            pk.y = *reinterpret_cast<unsigned int*>(&m1);
            pk.z = *reinterpret_cast<unsigned int*>(&m2);
            pk.w = *reinterpret_cast<unsigned int*>(&m3);
            *reinterpret_cast<uint4*>(&stage[(p - pb) * PADH + lane * 8]) = pk;
        }
        __syncthreads();

        // ---- coalesced writeback of this chunk: 128 channel-pairs x np
        // pixels; pair index = t + k*128 walked incrementally (p fastest).
        const int q = 128 / np;          // 5 for both np=25 and np=24
        const int r = 128 - q * np;      // 3 / 8
        int c2 = t / np;
        int pp = t - c2 * np;
        for (int k = 0; k < np; k++) {
            unsigned int v = *reinterpret_cast<const unsigned int*>(
                &stage[pp * PADH + 2 * c2]);
            __half2 h = *reinterpret_cast<__half2*>(&v);
            float2 f = __half22float2(h);
            ob[(2 * c2) * 49 + pb + pp]     = f.x;
            ob[(2 * c2 + 1) * 49 + pb + pp] = f.y;
            pp += r; c2 += q;
            if (pp >= np) { pp -= np; c2 += 1; }
        }
        __syncthreads();
    }
}

// -------------------------------------------------------------------------
extern "C" void kernel_launch(void* const* d_in, const int* in_sizes, int n_in,
                              void* d_out, int out_size) {
    const float* bottom = (const float*)d_in[0];
    const float* rois   = (const float*)d_in[1];
    if (n_in >= 2 && in_sizes[0] == NROI * 5) {
        bottom = (const float*)d_in[1];
        rois   = (const float*)d_in[0];
    }
    float* out = (float*)d_out;

    dim3 tgrid((HW_DIM + 31) / 32, C_DIM / 64);
    transpose_kernel<<<tgrid, dim3(32, 8)>>>(bottom);

    dim3 rgrid(NROI, 2);
    roi_pool_kernel<<<rgrid, 128>>>(rois, out);
}